// round 4
// baseline (speedup 1.0000x reference)
#include <cuda_runtime.h>

#define Hh  96
#define Ww  96
#define Dd  48
#define Cc  64
#define HW  (Hh * Ww)        // 9216
#define DHW (Dd * HW)        // 442368
#define P   32               // positions per block (divides Ww)

// Scratch: transposed feats [view][h][w][c] and imgs [view][h][w][4]
__device__ float g_feats_t[3 * HW * Cc];   // ~7.08 MB
__device__ float g_imgs_t [3 * HW * 4];    // ~0.44 MB

// ---------------------------------------------------------------------------
// Prepass: (C,H,W) -> (H,W,C) transpose per view via smem tile.
// ---------------------------------------------------------------------------
__global__ void __launch_bounds__(256) gridenc_transpose(
    const float* __restrict__ feats,   // (3, 64, 96, 96)
    const float* __restrict__ imgs)    // (3, 3, 96, 96)
{
    int v = blockIdx.x / Hh;
    int h = blockIdx.x % Hh;

    __shared__ float s[Ww * 65];

    const float* fsrc = feats + (size_t)(v * Cc) * HW + h * Ww;
    for (int i = threadIdx.x; i < Cc * Ww; i += 256) {
        int c = i / Ww;
        int w = i - c * Ww;
        s[w * 65 + c] = fsrc[c * HW + w];
    }
    __syncthreads();

    float* fdst = g_feats_t + (size_t)(v * HW + h * Ww) * Cc;
    for (int i = threadIdx.x; i < Ww * Cc; i += 256) {
        int w = i >> 6;
        int c = i & 63;
        fdst[i] = s[w * 65 + c];
    }

    const float* isrc = imgs + (size_t)(v * 3) * HW + h * Ww;
    float* idst = g_imgs_t + (size_t)(v * HW + h * Ww) * 4;
    for (int i = threadIdx.x; i < Ww * 4; i += 256) {
        int w = i >> 2;
        int c = i & 3;
        idst[i] = (c < 3) ? isrc[c * HW + w] : 0.0f;
    }
}

// ---------------------------------------------------------------------------
// Main kernel. Block = 32 consecutive positions within one (d,h) row.
// Phase 1 (warp 0): grid math -> packed smem params (float4 wts / int4 offs);
//                   img channels 0-8.
// Phase 2 (256 thr): thread = (position, 4-channel group). Dense channel
//                    gathers; params fetched with 5 vector LDS per pass.
// Phase 3 (256 thr): coalesced stores of the 64 variance channels.
// ---------------------------------------------------------------------------
__global__ void __launch_bounds__(256) gridenc_main(
    const float* __restrict__ imgs,    // (3, 3, 96, 96) - only view0 used
    const float* __restrict__ proj,    // (3, 3, 4)
    const float* __restrict__ depth,   // (48,)
    float* __restrict__ out)           // (73, 48, 96, 96)
{
    __shared__ float4 s_w[2][P];       // bilinear weights per view
    __shared__ int4   s_o[2][P];       // corner offsets, pre-multiplied by 64
    __shared__ float  s_inv[P];
    __shared__ float  s_var[Cc][P + 1];

    const int tid  = threadIdx.x;
    const int pos0 = blockIdx.x * P;

    // ---------------- Phase 1: one warp, one position per lane -------------
    if (tid < P) {
        int pos = pos0 + tid;
        int w   = pos % Ww;
        int h   = (pos / Ww) % Hh;
        int d   = pos / HW;
        int hw  = h * Ww + w;

        float dep = depth[d];
        float fw = (float)w, fh = (float)h;
        float nmask = 1.0f;

#pragma unroll
        for (int vi = 0; vi < 2; ++vi) {
            const float* Pm = proj + (vi + 1) * 12;
            float px = Pm[0] * fw + Pm[1] * fh + Pm[2]  + Pm[3]  / dep;
            float py = Pm[4] * fw + Pm[5] * fh + Pm[6]  + Pm[7]  / dep;
            float pz = Pm[8] * fw + Pm[9] * fh + Pm[10] + Pm[11] / dep;
            float gx = (px / pz) / 47.5f - 1.0f;
            float gy = (py / pz) / 47.5f - 1.0f;

            nmask += (gx > -1.0f && gx < 1.0f && gy > -1.0f && gy < 1.0f) ? 1.0f : 0.0f;

            float x = (gx + 1.0f) * 0.5f * 95.0f;
            float y = (gy + 1.0f) * 0.5f * 95.0f;

            float x0f = floorf(x), y0f = floorf(y);
            float fx1 = x - x0f, fy1 = y - y0f;
            float fx0 = 1.0f - fx1, fy0 = 1.0f - fy1;

            // per-corner validity (zeros padding); NaN coords -> all-false
            float vx0 = (x0f >=  0.0f && x0f <= 95.0f) ? 1.0f : 0.0f;
            float vx1 = (x0f >= -1.0f && x0f <= 94.0f) ? 1.0f : 0.0f;
            float vy0 = (y0f >=  0.0f && y0f <= 95.0f) ? 1.0f : 0.0f;
            float vy1 = (y0f >= -1.0f && y0f <= 94.0f) ? 1.0f : 0.0f;

            // per-corner INDEPENDENT clamping (matches reference)
            int ix0 = (int)fminf(fmaxf(x0f,        0.0f), 95.0f);
            int iy0 = (int)fminf(fmaxf(y0f,        0.0f), 95.0f);
            int ix1 = (int)fminf(fmaxf(x0f + 1.0f, 0.0f), 95.0f);
            int iy1 = (int)fminf(fmaxf(y0f + 1.0f, 0.0f), 95.0f);

            float w0 = fx0 * fy0 * vx0 * vy0;
            float w1 = fx1 * fy0 * vx1 * vy0;
            float w2 = fx0 * fy1 * vx0 * vy1;
            float w3 = fx1 * fy1 * vx1 * vy1;

            int vb = (vi + 1) * HW;
            int o0 = vb + iy0 * Ww + ix0;
            int o1 = vb + iy0 * Ww + ix1;
            int o2 = vb + iy1 * Ww + ix0;
            int o3 = vb + iy1 * Ww + ix1;

            s_w[vi][tid] = make_float4(w0, w1, w2, w3);
            s_o[vi][tid] = make_int4(o0 << 6, o1 << 6, o2 << 6, o3 << 6);

            // warped img channels (3 floats) for this view
            float4 t0 = *(const float4*)(g_imgs_t + (size_t)o0 * 4);
            float4 t1 = *(const float4*)(g_imgs_t + (size_t)o1 * 4);
            float4 t2 = *(const float4*)(g_imgs_t + (size_t)o2 * 4);
            float4 t3 = *(const float4*)(g_imgs_t + (size_t)o3 * 4);
            float ax = w0 * t0.x + w1 * t1.x + w2 * t2.x + w3 * t3.x;
            float ay = w0 * t0.y + w1 * t1.y + w2 * t2.y + w3 * t3.y;
            float az = w0 * t0.z + w1 * t1.z + w2 * t2.z + w3 * t3.z;
            out[(3 + 3 * vi + 0) * DHW + pos] = ax;
            out[(3 + 3 * vi + 1) * DHW + pos] = ay;
            out[(3 + 3 * vi + 2) * DHW + pos] = az;
        }

        s_inv[tid] = 1.0f / nmask;

        // channels 0-2: view0 imgs broadcast over depth
        out[0 * DHW + pos] = imgs[0 * HW + hw];
        out[1 * DHW + pos] = imgs[1 * HW + hw];
        out[2 * DHW + pos] = imgs[2 * HW + hw];
    }
    __syncthreads();

    // ---------------- Phase 2: dense channel gathers ------------------------
    {
        const int c4 = tid & 15;        // channel group: channels c4*4..+3
        const int pl = tid >> 4;        // 0..15
        const int cb = c4 << 2;

#pragma unroll
        for (int pass = 0; pass < 2; ++pass) {
            int p   = pass * 16 + pl;
            int pos = pos0 + p;
            int hw  = pos % HW;         // h*Ww + w

            float4 r = *(const float4*)(g_feats_t + hw * Cc + cb);
            float sx = r.x, sy = r.y, sz = r.z, sw_ = r.w;
            float qx = r.x * r.x, qy = r.y * r.y, qz = r.z * r.z, qw = r.w * r.w;

#pragma unroll
            for (int vi = 0; vi < 2; ++vi) {
                float4 wv = s_w[vi][p];
                int4   ov = s_o[vi][p];
                float4 a = *(const float4*)(g_feats_t + ov.x + cb);
                float4 b = *(const float4*)(g_feats_t + ov.y + cb);
                float4 c = *(const float4*)(g_feats_t + ov.z + cb);
                float4 e = *(const float4*)(g_feats_t + ov.w + cb);
                float mx = wv.x * a.x + wv.y * b.x + wv.z * c.x + wv.w * e.x;
                float my = wv.x * a.y + wv.y * b.y + wv.z * c.y + wv.w * e.y;
                float mz = wv.x * a.z + wv.y * b.z + wv.z * c.z + wv.w * e.z;
                float mw = wv.x * a.w + wv.y * b.w + wv.z * c.w + wv.w * e.w;
                sx += mx; sy += my; sz += mz; sw_ += mw;
                qx += mx * mx; qy += my * my; qz += mz * mz; qw += mw * mw;
            }

            float inv = s_inv[p];
            float mx = sx * inv, my = sy * inv, mz = sz * inv, mw = sw_ * inv;
            s_var[cb + 0][p] = qx * inv - mx * mx;
            s_var[cb + 1][p] = qy * inv - my * my;
            s_var[cb + 2][p] = qz * inv - mz * mz;
            s_var[cb + 3][p] = qw * inv - mw * mw;
        }
    }
    __syncthreads();

    // ---------------- Phase 3: coalesced variance stores --------------------
    {
        const int p  = tid & 31;
        const int cw = tid >> 5;        // warp id = channel offset
#pragma unroll
        for (int it = 0; it < 8; ++it) {
            int c = it * 8 + cw;
            out[(9 + c) * DHW + pos0 + p] = s_var[c][p];
        }
    }
}

// ---------------------------------------------------------------------------
// kernel_launch: graph-capturable, allocation-free.
// Inputs identified by element count (all distinct):
//   imgs=82944; feats=1769472; proj_mats=36; depth_values=48.
// ---------------------------------------------------------------------------
extern "C" void kernel_launch(void* const* d_in, const int* in_sizes, int n_in,
                              void* d_out, int out_size)
{
    const float* imgs  = nullptr;
    const float* feats = nullptr;
    const float* proj  = nullptr;
    const float* depth = nullptr;
    for (int i = 0; i < n_in; ++i) {
        switch (in_sizes[i]) {
            case 3 * 3 * HW:  imgs  = (const float*)d_in[i]; break;
            case 3 * Cc * HW: feats = (const float*)d_in[i]; break;
            case 36:          proj  = (const float*)d_in[i]; break;
            case Dd:          depth = (const float*)d_in[i]; break;
        }
    }
    float* out = (float*)d_out;

    gridenc_transpose<<<3 * Hh, 256>>>(feats, imgs);
    gridenc_main<<<DHW / P, 256>>>(imgs, proj, depth, out);
}

// round 5
// speedup vs baseline: 1.0622x; 1.0622x over previous
#include <cuda_runtime.h>
#include <cuda_fp16.h>

#define Hh  96
#define Ww  96
#define Dd  48
#define Cc  64
#define HW  (Hh * Ww)        // 9216
#define DHW (Dd * HW)        // 442368
#define P   32               // positions per block (divides Ww)

// Scratch: transposed feats [view][h][w][c] in fp16, imgs [view][h][w][4] fp32
__device__ __half g_feats_t[3 * HW * Cc];   // ~3.54 MB
__device__ float  g_imgs_t [3 * HW * 4];    // ~0.44 MB

// ---------------------------------------------------------------------------
// Prepass: (C,H,W) -> (H,W,C) transpose per view via smem tile; feats -> fp16.
// ---------------------------------------------------------------------------
__global__ void __launch_bounds__(256) gridenc_transpose(
    const float* __restrict__ feats,   // (3, 64, 96, 96)
    const float* __restrict__ imgs)    // (3, 3, 96, 96)
{
    int v = blockIdx.x / Hh;
    int h = blockIdx.x % Hh;

    __shared__ float s[Ww * 65];

    const float* fsrc = feats + (size_t)(v * Cc) * HW + h * Ww;
    for (int i = threadIdx.x; i < Cc * Ww; i += 256) {
        int c = i / Ww;
        int w = i - c * Ww;
        s[w * 65 + c] = fsrc[c * HW + w];
    }
    __syncthreads();

    __half* fdst = g_feats_t + (size_t)(v * HW + h * Ww) * Cc;
    for (int i = threadIdx.x; i < Ww * Cc; i += 256) {
        int w = i >> 6;
        int c = i & 63;
        fdst[i] = __float2half_rn(s[w * 65 + c]);
    }

    const float* isrc = imgs + (size_t)(v * 3) * HW + h * Ww;
    float* idst = g_imgs_t + (size_t)(v * HW + h * Ww) * 4;
    for (int i = threadIdx.x; i < Ww * 4; i += 256) {
        int w = i >> 2;
        int c = i & 3;
        idst[i] = (c < 3) ? isrc[c * HW + w] : 0.0f;
    }
}

// convert 8 packed halves (uint4) to 8 floats
__device__ __forceinline__ void h8_to_f(uint4 v, float* f) {
    float2 t;
    t = __half22float2(*(__half2*)&v.x); f[0] = t.x; f[1] = t.y;
    t = __half22float2(*(__half2*)&v.y); f[2] = t.x; f[3] = t.y;
    t = __half22float2(*(__half2*)&v.z); f[4] = t.x; f[5] = t.y;
    t = __half22float2(*(__half2*)&v.w); f[6] = t.x; f[7] = t.y;
}

// ---------------------------------------------------------------------------
// Main kernel. Block = 32 consecutive positions within one (d,h) row.
// Phase 1 (warp 0): grid math -> packed smem params; img channels 0-8.
// Phase 2 (256 thr): thread = (position p = tid>>3, 8-channel group c8 =
//                    tid&7). Each corner gather = lane-dense 128B fp16 vector.
//                    fp32 weights/accumulation. Variance -> s_var[c][p].
// Phase 3 (256 thr): coalesced stores of the 64 variance channels.
// ---------------------------------------------------------------------------
__global__ void __launch_bounds__(256) gridenc_main(
    const float* __restrict__ imgs,    // (3, 3, 96, 96) - only view0 used
    const float* __restrict__ proj,    // (3, 3, 4)
    const float* __restrict__ depth,   // (48,)
    float* __restrict__ out)           // (73, 48, 96, 96)
{
    __shared__ float4 s_w[2][P];       // bilinear weights per view
    __shared__ int4   s_o[2][P];       // corner offsets in half-elements (off*64)
    __shared__ float  s_inv[P];
    __shared__ int    s_hw [P];
    __shared__ float  s_var[Cc][P + 1];

    const int tid  = threadIdx.x;
    const int pos0 = blockIdx.x * P;

    // ---------------- Phase 1: one warp, one position per lane -------------
    if (tid < P) {
        int pos = pos0 + tid;
        int w   = pos % Ww;
        int h   = (pos / Ww) % Hh;
        int d   = pos / HW;
        int hw  = h * Ww + w;
        s_hw[tid] = hw;

        float dep = depth[d];
        float fw = (float)w, fh = (float)h;
        float nmask = 1.0f;

#pragma unroll
        for (int vi = 0; vi < 2; ++vi) {
            const float* Pm = proj + (vi + 1) * 12;
            float px = Pm[0] * fw + Pm[1] * fh + Pm[2]  + Pm[3]  / dep;
            float py = Pm[4] * fw + Pm[5] * fh + Pm[6]  + Pm[7]  / dep;
            float pz = Pm[8] * fw + Pm[9] * fh + Pm[10] + Pm[11] / dep;
            float gx = (px / pz) / 47.5f - 1.0f;
            float gy = (py / pz) / 47.5f - 1.0f;

            nmask += (gx > -1.0f && gx < 1.0f && gy > -1.0f && gy < 1.0f) ? 1.0f : 0.0f;

            float x = (gx + 1.0f) * 0.5f * 95.0f;
            float y = (gy + 1.0f) * 0.5f * 95.0f;

            float x0f = floorf(x), y0f = floorf(y);
            float fx1 = x - x0f, fy1 = y - y0f;
            float fx0 = 1.0f - fx1, fy0 = 1.0f - fy1;

            // per-corner validity (zeros padding); NaN coords -> all-false
            float vx0 = (x0f >=  0.0f && x0f <= 95.0f) ? 1.0f : 0.0f;
            float vx1 = (x0f >= -1.0f && x0f <= 94.0f) ? 1.0f : 0.0f;
            float vy0 = (y0f >=  0.0f && y0f <= 95.0f) ? 1.0f : 0.0f;
            float vy1 = (y0f >= -1.0f && y0f <= 94.0f) ? 1.0f : 0.0f;

            // per-corner INDEPENDENT clamping (matches reference)
            int ix0 = (int)fminf(fmaxf(x0f,        0.0f), 95.0f);
            int iy0 = (int)fminf(fmaxf(y0f,        0.0f), 95.0f);
            int ix1 = (int)fminf(fmaxf(x0f + 1.0f, 0.0f), 95.0f);
            int iy1 = (int)fminf(fmaxf(y0f + 1.0f, 0.0f), 95.0f);

            float w0 = fx0 * fy0 * vx0 * vy0;
            float w1 = fx1 * fy0 * vx1 * vy0;
            float w2 = fx0 * fy1 * vx0 * vy1;
            float w3 = fx1 * fy1 * vx1 * vy1;

            int vb = (vi + 1) * HW;
            int o0 = vb + iy0 * Ww + ix0;
            int o1 = vb + iy0 * Ww + ix1;
            int o2 = vb + iy1 * Ww + ix0;
            int o3 = vb + iy1 * Ww + ix1;

            s_w[vi][tid] = make_float4(w0, w1, w2, w3);
            s_o[vi][tid] = make_int4(o0 << 6, o1 << 6, o2 << 6, o3 << 6);

            // warped img channels (3 floats) for this view (fp32 path)
            float4 t0 = *(const float4*)(g_imgs_t + (size_t)o0 * 4);
            float4 t1 = *(const float4*)(g_imgs_t + (size_t)o1 * 4);
            float4 t2 = *(const float4*)(g_imgs_t + (size_t)o2 * 4);
            float4 t3 = *(const float4*)(g_imgs_t + (size_t)o3 * 4);
            float ax = w0 * t0.x + w1 * t1.x + w2 * t2.x + w3 * t3.x;
            float ay = w0 * t0.y + w1 * t1.y + w2 * t2.y + w3 * t3.y;
            float az = w0 * t0.z + w1 * t1.z + w2 * t2.z + w3 * t3.z;
            out[(3 + 3 * vi + 0) * DHW + pos] = ax;
            out[(3 + 3 * vi + 1) * DHW + pos] = ay;
            out[(3 + 3 * vi + 2) * DHW + pos] = az;
        }

        s_inv[tid] = 1.0f / nmask;

        // channels 0-2: view0 imgs broadcast over depth
        out[0 * DHW + pos] = imgs[0 * HW + hw];
        out[1 * DHW + pos] = imgs[1 * HW + hw];
        out[2 * DHW + pos] = imgs[2 * HW + hw];
    }
    __syncthreads();

    // ---------------- Phase 2: dense fp16 channel gathers, single pass ------
    {
        const int c8 = tid & 7;         // channels c8*8 .. c8*8+7
        const int p  = tid >> 3;        // 0..31
        const int ce = c8 << 3;         // channel element offset

        const int hw = s_hw[p];

        float sacc[8], qacc[8], f[8];

        uint4 rv = *(const uint4*)(g_feats_t + hw * Cc + ce);
        h8_to_f(rv, f);
#pragma unroll
        for (int j = 0; j < 8; ++j) { sacc[j] = f[j]; qacc[j] = f[j] * f[j]; }

#pragma unroll
        for (int vi = 0; vi < 2; ++vi) {
            float4 wv = s_w[vi][p];
            int4   ov = s_o[vi][p];
            uint4 va = *(const uint4*)(g_feats_t + ov.x + ce);
            uint4 vb = *(const uint4*)(g_feats_t + ov.y + ce);
            uint4 vc = *(const uint4*)(g_feats_t + ov.z + ce);
            uint4 ve = *(const uint4*)(g_feats_t + ov.w + ce);
            float fa[8], fb[8], fc[8], fe[8];
            h8_to_f(va, fa); h8_to_f(vb, fb); h8_to_f(vc, fc); h8_to_f(ve, fe);
#pragma unroll
            for (int j = 0; j < 8; ++j) {
                float m = wv.x * fa[j] + wv.y * fb[j] + wv.z * fc[j] + wv.w * fe[j];
                sacc[j] += m;
                qacc[j] += m * m;
            }
        }

        float inv = s_inv[p];
#pragma unroll
        for (int j = 0; j < 8; ++j) {
            float m = sacc[j] * inv;
            s_var[ce + j][p] = qacc[j] * inv - m * m;
        }
    }
    __syncthreads();

    // ---------------- Phase 3: coalesced variance stores --------------------
    {
        const int p  = tid & 31;
        const int cw = tid >> 5;        // warp id = channel offset
#pragma unroll
        for (int it = 0; it < 8; ++it) {
            int c = it * 8 + cw;
            out[(9 + c) * DHW + pos0 + p] = s_var[c][p];
        }
    }
}

// ---------------------------------------------------------------------------
// kernel_launch: graph-capturable, allocation-free.
// Inputs identified by element count (all distinct):
//   imgs=82944; feats=1769472; proj_mats=36; depth_values=48.
// ---------------------------------------------------------------------------
extern "C" void kernel_launch(void* const* d_in, const int* in_sizes, int n_in,
                              void* d_out, int out_size)
{
    const float* imgs  = nullptr;
    const float* feats = nullptr;
    const float* proj  = nullptr;
    const float* depth = nullptr;
    for (int i = 0; i < n_in; ++i) {
        switch (in_sizes[i]) {
            case 3 * 3 * HW:  imgs  = (const float*)d_in[i]; break;
            case 3 * Cc * HW: feats = (const float*)d_in[i]; break;
            case 36:          proj  = (const float*)d_in[i]; break;
            case Dd:          depth = (const float*)d_in[i]; break;
        }
    }
    float* out = (float*)d_out;

    gridenc_transpose<<<3 * Hh, 256>>>(feats, imgs);
    gridenc_main<<<DHW / P, 256>>>(imgs, proj, depth, out);
}

// round 6
// speedup vs baseline: 1.3760x; 1.2954x over previous
#include <cuda_runtime.h>
#include <cuda_fp16.h>

#define Hh  96
#define Ww  96
#define Dd  48
#define Cc  64
#define HW  (Hh * Ww)        // 9216
#define DHW (Dd * HW)        // 442368
#define P   32               // positions per block (divides Ww)

// Scratch: transposed feats [view][h][w][c] in fp16, imgs [view][h][w][4] fp32
__device__ __half g_feats_t[3 * HW * Cc];   // ~3.54 MB
__device__ float  g_imgs_t [3 * HW * 4];    // ~0.44 MB

// ---------------------------------------------------------------------------
// Prepass: (C,H,W) -> (H,W,C) transpose per view via smem tile; feats -> fp16.
// ---------------------------------------------------------------------------
__global__ void __launch_bounds__(256) gridenc_transpose(
    const float* __restrict__ feats,   // (3, 64, 96, 96)
    const float* __restrict__ imgs)    // (3, 3, 96, 96)
{
    int v = blockIdx.x / Hh;
    int h = blockIdx.x % Hh;

    __shared__ float s[Ww * 65];

    const float* fsrc = feats + (size_t)(v * Cc) * HW + h * Ww;
    for (int i = threadIdx.x; i < Cc * Ww; i += 256) {
        int c = i / Ww;
        int w = i - c * Ww;
        s[w * 65 + c] = fsrc[c * HW + w];
    }
    __syncthreads();

    __half* fdst = g_feats_t + (size_t)(v * HW + h * Ww) * Cc;
    for (int i = threadIdx.x; i < Ww * Cc; i += 256) {
        int w = i >> 6;
        int c = i & 63;
        fdst[i] = __float2half_rn(s[w * 65 + c]);
    }

    const float* isrc = imgs + (size_t)(v * 3) * HW + h * Ww;
    float* idst = g_imgs_t + (size_t)(v * HW + h * Ww) * 4;
    for (int i = threadIdx.x; i < Ww * 4; i += 256) {
        int w = i >> 2;
        int c = i & 3;
        idst[i] = (c < 3) ? isrc[c * HW + w] : 0.0f;
    }
}

// convert 8 packed halves (uint4) to 8 floats
__device__ __forceinline__ void h8_to_f(uint4 v, float* f) {
    float2 t;
    t = __half22float2(*(__half2*)&v.x); f[0] = t.x; f[1] = t.y;
    t = __half22float2(*(__half2*)&v.y); f[2] = t.x; f[3] = t.y;
    t = __half22float2(*(__half2*)&v.z); f[4] = t.x; f[5] = t.y;
    t = __half22float2(*(__half2*)&v.w); f[6] = t.x; f[7] = t.y;
}

// ---------------------------------------------------------------------------
// Main kernel. Block = 32 consecutive positions within one (d,h) row.
// Phase 0 (all): prefetch ref-feature vector (position-only dependence).
// Phase 1: warp0 = geometry+img-warp for view1; warp1 = same for view2;
//          warp2 = view0 img broadcast channels. Warps 3-7 idle briefly
//          (their ref LDG is already in flight).
// Phase 2 (256 thr): thread = (p = tid>>3, c8 = tid&7); dense fp16 gathers,
//          fp32 blend/accumulate; variance -> s_var[c][p].
// Phase 3: coalesced stores of the 64 variance channels.
// ---------------------------------------------------------------------------
__global__ void __launch_bounds__(256) gridenc_main(
    const float* __restrict__ imgs,    // (3, 3, 96, 96) - only view0 used
    const float* __restrict__ proj,    // (3, 3, 4)
    const float* __restrict__ depth,   // (48,)
    float* __restrict__ out)           // (73, 48, 96, 96)
{
    __shared__ float4 s_w[2][P];       // bilinear weights per view
    __shared__ int4   s_o[2][P];       // corner offsets in half-elems (off*64)
    __shared__ float  s_m[2][P];       // in-range flag per view
    __shared__ float  s_var[Cc][P + 1];

    const int tid  = threadIdx.x;
    const int pos0 = blockIdx.x * P;
    const int hw0  = pos0 % HW;        // block-uniform (P divides row)

    // ---------------- Phase 0: prefetch ref feature vector ------------------
    const int c8 = tid & 7;            // channels c8*8 .. c8*8+7
    const int p2 = tid >> 3;           // 0..31
    const int ce = c8 << 3;
    uint4 rv = *(const uint4*)(g_feats_t + (hw0 + p2) * Cc + ce);

    // ---------------- Phase 1: split across warps 0-2 -----------------------
    if (tid < 64) {
        const int vi = tid >> 5;       // view index (0 -> src view 1)
        const int p  = tid & 31;
        int pos = pos0 + p;
        int w   = (hw0 + p) % Ww;
        int h   = (hw0 + p) / Ww;
        int d   = pos / HW;

        float dep = depth[d];
        float fw = (float)w, fh = (float)h;

        const float* Pm = proj + (vi + 1) * 12;
        float px = Pm[0] * fw + Pm[1] * fh + Pm[2]  + Pm[3]  / dep;
        float py = Pm[4] * fw + Pm[5] * fh + Pm[6]  + Pm[7]  / dep;
        float pz = Pm[8] * fw + Pm[9] * fh + Pm[10] + Pm[11] / dep;
        float gx = (px / pz) / 47.5f - 1.0f;
        float gy = (py / pz) / 47.5f - 1.0f;

        s_m[vi][p] = (gx > -1.0f && gx < 1.0f && gy > -1.0f && gy < 1.0f) ? 1.0f : 0.0f;

        float x = (gx + 1.0f) * 0.5f * 95.0f;
        float y = (gy + 1.0f) * 0.5f * 95.0f;

        float x0f = floorf(x), y0f = floorf(y);
        float fx1 = x - x0f, fy1 = y - y0f;
        float fx0 = 1.0f - fx1, fy0 = 1.0f - fy1;

        // per-corner validity (zeros padding); NaN coords -> all-false
        float vx0 = (x0f >=  0.0f && x0f <= 95.0f) ? 1.0f : 0.0f;
        float vx1 = (x0f >= -1.0f && x0f <= 94.0f) ? 1.0f : 0.0f;
        float vy0 = (y0f >=  0.0f && y0f <= 95.0f) ? 1.0f : 0.0f;
        float vy1 = (y0f >= -1.0f && y0f <= 94.0f) ? 1.0f : 0.0f;

        // per-corner INDEPENDENT clamping (matches reference)
        int ix0 = (int)fminf(fmaxf(x0f,        0.0f), 95.0f);
        int iy0 = (int)fminf(fmaxf(y0f,        0.0f), 95.0f);
        int ix1 = (int)fminf(fmaxf(x0f + 1.0f, 0.0f), 95.0f);
        int iy1 = (int)fminf(fmaxf(y0f + 1.0f, 0.0f), 95.0f);

        float w0 = fx0 * fy0 * vx0 * vy0;
        float w1 = fx1 * fy0 * vx1 * vy0;
        float w2 = fx0 * fy1 * vx0 * vy1;
        float w3 = fx1 * fy1 * vx1 * vy1;

        int vb = (vi + 1) * HW;
        int o0 = vb + iy0 * Ww + ix0;
        int o1 = vb + iy0 * Ww + ix1;
        int o2 = vb + iy1 * Ww + ix0;
        int o3 = vb + iy1 * Ww + ix1;

        s_w[vi][p] = make_float4(w0, w1, w2, w3);
        s_o[vi][p] = make_int4(o0 << 6, o1 << 6, o2 << 6, o3 << 6);

        // warped img channels (3 floats) for this view (fp32 path)
        float4 t0 = *(const float4*)(g_imgs_t + (size_t)o0 * 4);
        float4 t1 = *(const float4*)(g_imgs_t + (size_t)o1 * 4);
        float4 t2 = *(const float4*)(g_imgs_t + (size_t)o2 * 4);
        float4 t3 = *(const float4*)(g_imgs_t + (size_t)o3 * 4);
        out[(3 + 3 * vi + 0) * DHW + pos] = w0 * t0.x + w1 * t1.x + w2 * t2.x + w3 * t3.x;
        out[(3 + 3 * vi + 1) * DHW + pos] = w0 * t0.y + w1 * t1.y + w2 * t2.y + w3 * t3.y;
        out[(3 + 3 * vi + 2) * DHW + pos] = w0 * t0.z + w1 * t1.z + w2 * t2.z + w3 * t3.z;
    } else if (tid < 96) {
        const int p  = tid & 31;
        int pos = pos0 + p;
        int hw  = hw0 + p;
        out[0 * DHW + pos] = imgs[0 * HW + hw];
        out[1 * DHW + pos] = imgs[1 * HW + hw];
        out[2 * DHW + pos] = imgs[2 * HW + hw];
    }
    __syncthreads();

    // ---------------- Phase 2: dense fp16 channel gathers -------------------
    {
        float sacc[8], qacc[8], f[8];
        h8_to_f(rv, f);
#pragma unroll
        for (int j = 0; j < 8; ++j) { sacc[j] = f[j]; qacc[j] = f[j] * f[j]; }

#pragma unroll
        for (int vi = 0; vi < 2; ++vi) {
            float4 wv = s_w[vi][p2];
            int4   ov = s_o[vi][p2];
            uint4 va = *(const uint4*)(g_feats_t + ov.x + ce);
            uint4 vb = *(const uint4*)(g_feats_t + ov.y + ce);
            uint4 vc = *(const uint4*)(g_feats_t + ov.z + ce);
            uint4 ve = *(const uint4*)(g_feats_t + ov.w + ce);
            float fa[8], fb[8], fc[8], fe[8];
            h8_to_f(va, fa); h8_to_f(vb, fb); h8_to_f(vc, fc); h8_to_f(ve, fe);
#pragma unroll
            for (int j = 0; j < 8; ++j) {
                float m = wv.x * fa[j] + wv.y * fb[j] + wv.z * fc[j] + wv.w * fe[j];
                sacc[j] += m;
                qacc[j] += m * m;
            }
        }

        float nm  = 1.0f + s_m[0][p2] + s_m[1][p2];
        float inv = 1.0f / nm;
#pragma unroll
        for (int j = 0; j < 8; ++j) {
            float m = sacc[j] * inv;
            s_var[ce + j][p2] = qacc[j] * inv - m * m;
        }
    }
    __syncthreads();

    // ---------------- Phase 3: coalesced variance stores --------------------
    {
        const int p  = tid & 31;
        const int cw = tid >> 5;        // warp id = channel offset
#pragma unroll
        for (int it = 0; it < 8; ++it) {
            int c = it * 8 + cw;
            out[(9 + c) * DHW + pos0 + p] = s_var[c][p];
        }
    }
}

// ---------------------------------------------------------------------------
// kernel_launch: graph-capturable, allocation-free.
// Inputs identified by element count (all distinct):
//   imgs=82944; feats=1769472; proj_mats=36; depth_values=48.
// ---------------------------------------------------------------------------
extern "C" void kernel_launch(void* const* d_in, const int* in_sizes, int n_in,
                              void* d_out, int out_size)
{
    const float* imgs  = nullptr;
    const float* feats = nullptr;
    const float* proj  = nullptr;
    const float* depth = nullptr;
    for (int i = 0; i < n_in; ++i) {
        switch (in_sizes[i]) {
            case 3 * 3 * HW:  imgs  = (const float*)d_in[i]; break;
            case 3 * Cc * HW: feats = (const float*)d_in[i]; break;
            case 36:          proj  = (const float*)d_in[i]; break;
            case Dd:          depth = (const float*)d_in[i]; break;
        }
    }
    float* out = (float*)d_out;

    gridenc_transpose<<<3 * Hh, 256>>>(feats, imgs);
    gridenc_main<<<DHW / P, 256>>>(imgs, proj, depth, out);
}

// round 7
// speedup vs baseline: 1.4015x; 1.0185x over previous
#include <cuda_runtime.h>
#include <cuda_fp16.h>

#define Hh  96
#define Ww  96
#define Dd  48
#define Cc  64
#define HW  (Hh * Ww)        // 9216
#define DHW (Dd * HW)        // 442368
#define P   32               // positions per block (divides Ww)

// Scratch: transposed feats [view][h][w][c] in fp16, imgs [view][h][w][4] fp32
__device__ __half g_feats_t[3 * HW * Cc];   // ~3.54 MB
__device__ float  g_imgs_t [3 * HW * 4];    // ~0.44 MB

// ---------------------------------------------------------------------------
// Prepass: (C,H,W) -> (H,W,C) transpose per view via smem tile; feats -> fp16.
// ---------------------------------------------------------------------------
__global__ void __launch_bounds__(256) gridenc_transpose(
    const float* __restrict__ feats,   // (3, 64, 96, 96)
    const float* __restrict__ imgs)    // (3, 3, 96, 96)
{
    int v = blockIdx.x / Hh;
    int h = blockIdx.x % Hh;

    __shared__ float s[Ww * 65];

    const float* fsrc = feats + (size_t)(v * Cc) * HW + h * Ww;
    for (int i = threadIdx.x; i < Cc * Ww; i += 256) {
        int c = i / Ww;
        int w = i - c * Ww;
        s[w * 65 + c] = fsrc[c * HW + w];
    }
    __syncthreads();

    __half* fdst = g_feats_t + (size_t)(v * HW + h * Ww) * Cc;
    for (int i = threadIdx.x; i < Ww * Cc; i += 256) {
        int w = i >> 6;
        int c = i & 63;
        fdst[i] = __float2half_rn(s[w * 65 + c]);
    }

    const float* isrc = imgs + (size_t)(v * 3) * HW + h * Ww;
    float* idst = g_imgs_t + (size_t)(v * HW + h * Ww) * 4;
    for (int i = threadIdx.x; i < Ww * 4; i += 256) {
        int w = i >> 2;
        int c = i & 3;
        idst[i] = (c < 3) ? isrc[c * HW + w] : 0.0f;
    }
}

// ---------------------------------------------------------------------------
// Main kernel. Block = 32 consecutive positions within one (d,h) row.
// Phase 0 (all): prefetch ref-feature vector (position-only dependence).
// Phase 1: warp0 = geometry+img-warp for view1; warp1 = same for view2;
//          warp2 = view0 img broadcast channels. Weights stored as
//          duplicated half2 quads for phase-2 HFMA2 blending.
// Phase 2 (256 thr): thread = (p = tid>>3, c8 = tid&7); dense fp16 gathers,
//          half2 corner blend, fp32 accumulation; variance -> s_var[c][p].
// Phase 3: coalesced stores of the 64 variance channels.
// ---------------------------------------------------------------------------
__global__ void __launch_bounds__(256) gridenc_main(
    const float* __restrict__ imgs,    // (3, 3, 96, 96) - only view0 used
    const float* __restrict__ proj,    // (3, 3, 4)
    const float* __restrict__ depth,   // (48,)
    float* __restrict__ out)           // (73, 48, 96, 96)
{
    __shared__ uint4  s_wh[2][P];      // 4 bilinear weights as duplicated half2
    __shared__ int4   s_o[2][P];       // corner offsets in half-elems (off*64)
    __shared__ float  s_m[2][P];       // in-range flag per view
    __shared__ float  s_var[Cc][P + 1];

    const int tid  = threadIdx.x;
    const int pos0 = blockIdx.x * P;
    const int hw0  = pos0 % HW;        // block-uniform (P divides row)

    // ---------------- Phase 0: prefetch ref feature vector ------------------
    const int c8 = tid & 7;            // channels c8*8 .. c8*8+7
    const int p2 = tid >> 3;           // 0..31
    const int ce = c8 << 3;
    uint4 rv = *(const uint4*)(g_feats_t + (hw0 + p2) * Cc + ce);

    // ---------------- Phase 1: split across warps 0-2 -----------------------
    if (tid < 64) {
        const int vi = tid >> 5;       // view index (0 -> src view 1)
        const int p  = tid & 31;
        int pos = pos0 + p;
        int w   = (hw0 + p) % Ww;
        int h   = (hw0 + p) / Ww;
        int d   = pos / HW;

        float dep = depth[d];
        float fw = (float)w, fh = (float)h;

        const float* Pm = proj + (vi + 1) * 12;
        float px = Pm[0] * fw + Pm[1] * fh + Pm[2]  + Pm[3]  / dep;
        float py = Pm[4] * fw + Pm[5] * fh + Pm[6]  + Pm[7]  / dep;
        float pz = Pm[8] * fw + Pm[9] * fh + Pm[10] + Pm[11] / dep;
        float gx = (px / pz) / 47.5f - 1.0f;
        float gy = (py / pz) / 47.5f - 1.0f;

        s_m[vi][p] = (gx > -1.0f && gx < 1.0f && gy > -1.0f && gy < 1.0f) ? 1.0f : 0.0f;

        float x = (gx + 1.0f) * 0.5f * 95.0f;
        float y = (gy + 1.0f) * 0.5f * 95.0f;

        float x0f = floorf(x), y0f = floorf(y);
        float fx1 = x - x0f, fy1 = y - y0f;
        float fx0 = 1.0f - fx1, fy0 = 1.0f - fy1;

        // per-corner validity (zeros padding); NaN coords -> all-false
        float vx0 = (x0f >=  0.0f && x0f <= 95.0f) ? 1.0f : 0.0f;
        float vx1 = (x0f >= -1.0f && x0f <= 94.0f) ? 1.0f : 0.0f;
        float vy0 = (y0f >=  0.0f && y0f <= 95.0f) ? 1.0f : 0.0f;
        float vy1 = (y0f >= -1.0f && y0f <= 94.0f) ? 1.0f : 0.0f;

        // per-corner INDEPENDENT clamping (matches reference)
        int ix0 = (int)fminf(fmaxf(x0f,        0.0f), 95.0f);
        int iy0 = (int)fminf(fmaxf(y0f,        0.0f), 95.0f);
        int ix1 = (int)fminf(fmaxf(x0f + 1.0f, 0.0f), 95.0f);
        int iy1 = (int)fminf(fmaxf(y0f + 1.0f, 0.0f), 95.0f);

        float w0 = fx0 * fy0 * vx0 * vy0;
        float w1 = fx1 * fy0 * vx1 * vy0;
        float w2 = fx0 * fy1 * vx0 * vy1;
        float w3 = fx1 * fy1 * vx1 * vy1;

        int vb = (vi + 1) * HW;
        int o0 = vb + iy0 * Ww + ix0;
        int o1 = vb + iy0 * Ww + ix1;
        int o2 = vb + iy1 * Ww + ix0;
        int o3 = vb + iy1 * Ww + ix1;

        // weights as duplicated half2 (for HFMA2 blending in phase 2)
        uint4 wq;
        __half2 h0 = __float2half2_rn(w0);
        __half2 h1 = __float2half2_rn(w1);
        __half2 h2 = __float2half2_rn(w2);
        __half2 h3 = __float2half2_rn(w3);
        wq.x = *(unsigned*)&h0; wq.y = *(unsigned*)&h1;
        wq.z = *(unsigned*)&h2; wq.w = *(unsigned*)&h3;
        s_wh[vi][p] = wq;
        s_o[vi][p] = make_int4(o0 << 6, o1 << 6, o2 << 6, o3 << 6);

        // warped img channels (3 floats) for this view (fp32 path)
        float4 t0 = *(const float4*)(g_imgs_t + (size_t)o0 * 4);
        float4 t1 = *(const float4*)(g_imgs_t + (size_t)o1 * 4);
        float4 t2 = *(const float4*)(g_imgs_t + (size_t)o2 * 4);
        float4 t3 = *(const float4*)(g_imgs_t + (size_t)o3 * 4);
        out[(3 + 3 * vi + 0) * DHW + pos] = w0 * t0.x + w1 * t1.x + w2 * t2.x + w3 * t3.x;
        out[(3 + 3 * vi + 1) * DHW + pos] = w0 * t0.y + w1 * t1.y + w2 * t2.y + w3 * t3.y;
        out[(3 + 3 * vi + 2) * DHW + pos] = w0 * t0.z + w1 * t1.z + w2 * t2.z + w3 * t3.z;
    } else if (tid < 96) {
        const int p  = tid & 31;
        int pos = pos0 + p;
        int hw  = hw0 + p;
        out[0 * DHW + pos] = imgs[0 * HW + hw];
        out[1 * DHW + pos] = imgs[1 * HW + hw];
        out[2 * DHW + pos] = imgs[2 * HW + hw];
    }
    __syncthreads();

    // ---------------- Phase 2: half2 corner blend, fp32 accumulate ----------
    {
        float sacc[8], qacc[8];
        {
            const __half2* r2 = (const __half2*)&rv;
#pragma unroll
            for (int k = 0; k < 4; ++k) {
                float2 f = __half22float2(r2[k]);
                sacc[2 * k]     = f.x;  qacc[2 * k]     = f.x * f.x;
                sacc[2 * k + 1] = f.y;  qacc[2 * k + 1] = f.y * f.y;
            }
        }

#pragma unroll
        for (int vi = 0; vi < 2; ++vi) {
            uint4 wq = s_wh[vi][p2];
            __half2 w0 = *(__half2*)&wq.x, w1 = *(__half2*)&wq.y;
            __half2 w2 = *(__half2*)&wq.z, w3 = *(__half2*)&wq.w;
            int4 ov = s_o[vi][p2];
            uint4 va = *(const uint4*)(g_feats_t + ov.x + ce);
            uint4 vb = *(const uint4*)(g_feats_t + ov.y + ce);
            uint4 vc = *(const uint4*)(g_feats_t + ov.z + ce);
            uint4 ve = *(const uint4*)(g_feats_t + ov.w + ce);
            const __half2* a2 = (const __half2*)&va;
            const __half2* b2 = (const __half2*)&vb;
            const __half2* c2 = (const __half2*)&vc;
            const __half2* e2 = (const __half2*)&ve;
#pragma unroll
            for (int k = 0; k < 4; ++k) {
                __half2 m2 = __hmul2(w0, a2[k]);
                m2 = __hfma2(w1, b2[k], m2);
                m2 = __hfma2(w2, c2[k], m2);
                m2 = __hfma2(w3, e2[k], m2);
                float2 mf = __half22float2(m2);
                sacc[2 * k]     += mf.x;  qacc[2 * k]     += mf.x * mf.x;
                sacc[2 * k + 1] += mf.y;  qacc[2 * k + 1] += mf.y * mf.y;
            }
        }

        float nm  = 1.0f + s_m[0][p2] + s_m[1][p2];
        float inv = 1.0f / nm;
#pragma unroll
        for (int j = 0; j < 8; ++j) {
            float m = sacc[j] * inv;
            s_var[ce + j][p2] = qacc[j] * inv - m * m;
        }
    }
    __syncthreads();

    // ---------------- Phase 3: coalesced variance stores --------------------
    {
        const int p  = tid & 31;
        const int cw = tid >> 5;        // warp id = channel offset
#pragma unroll
        for (int it = 0; it < 8; ++it) {
            int c = it * 8 + cw;
            out[(9 + c) * DHW + pos0 + p] = s_var[c][p];
        }
    }
}

// ---------------------------------------------------------------------------
// kernel_launch: graph-capturable, allocation-free.
// Inputs identified by element count (all distinct):
//   imgs=82944; feats=1769472; proj_mats=36; depth_values=48.
// ---------------------------------------------------------------------------
extern "C" void kernel_launch(void* const* d_in, const int* in_sizes, int n_in,
                              void* d_out, int out_size)
{
    const float* imgs  = nullptr;
    const float* feats = nullptr;
    const float* proj  = nullptr;
    const float* depth = nullptr;
    for (int i = 0; i < n_in; ++i) {
        switch (in_sizes[i]) {
            case 3 * 3 * HW:  imgs  = (const float*)d_in[i]; break;
            case 3 * Cc * HW: feats = (const float*)d_in[i]; break;
            case 36:          proj  = (const float*)d_in[i]; break;
            case Dd:          depth = (const float*)d_in[i]; break;
        }
    }
    float* out = (float*)d_out;

    gridenc_transpose<<<3 * Hh, 256>>>(feats, imgs);
    gridenc_main<<<DHW / P, 256>>>(imgs, proj, depth, out);
}